// round 17
// baseline (speedup 1.0000x reference)
#include <cuda_runtime.h>
#include <math.h>
#include <stdint.h>

#define BB   8
#define CC   256
#define ICn  128
#define NPIX 4096
#define NPm  1024

// ---------- bf16 helpers ----------
__device__ __forceinline__ uint32_t packbf(float e0, float e1) {
    uint32_t r; asm("cvt.rn.bf16x2.f32 %0, %1, %2;" : "=r"(r) : "f"(e1), "f"(e0)); return r;
}
__device__ __forceinline__ void splitpair(float v0, float v1, uint32_t &hp, uint32_t &lp) {
    hp = packbf(v0, v1);
    float h0 = __uint_as_float(hp << 16);
    float h1 = __uint_as_float(hp & 0xffff0000u);
    lp = packbf(v0 - h0, v1 - h1);
}

// mma.sync m16n8k16 bf16: C += A*B
__device__ __forceinline__ void mma16(float* c, const uint32_t* a, const uint32_t* b) {
    asm volatile("mma.sync.aligned.m16n8k16.row.col.f32.bf16.bf16.f32 "
        "{%0,%1,%2,%3}, {%4,%5,%6,%7}, {%8,%9}, {%0,%1,%2,%3};"
        : "+f"(c[0]), "+f"(c[1]), "+f"(c[2]), "+f"(c[3])
        : "r"(a[0]), "r"(a[1]), "r"(a[2]), "r"(a[3]), "r"(b[0]), "r"(b[1]));
}

// ---------- cp.async helpers ----------
__device__ __forceinline__ uint32_t smem_u32addr(const void* p) {
    uint32_t a;
    asm("{ .reg .u64 t; cvta.to.shared.u64 t, %1; cvt.u32.u64 %0, t; }" : "=r"(a) : "l"(p));
    return a;
}
__device__ __forceinline__ void cp_async16(uint32_t dst, const void* src) {
    asm volatile("cp.async.cg.shared.global [%0], [%1], 16;" :: "r"(dst), "l"(src));
}
#define CP_COMMIT() asm volatile("cp.async.commit_group;" ::: "memory")
#define CP_WAIT(n)  asm volatile("cp.async.wait_group %0;" :: "n"(n) : "memory")

// ---------- scratch: everything in frag format (hi/lo bf16x2) ----------
__device__ uint32_t d_wpH[3 * 16384 + 2 * 8192]; // proj W B-frags; out W at 49152
__device__ uint32_t d_wpL[3 * 16384 + 2 * 8192];
__device__ uint32_t d_thH[BB * 32 * 8192];       // theta A-frags [b][rt][ww][s][128]
__device__ uint32_t d_thL[BB * 32 * 8192];
__device__ uint32_t d_phH[BB * 16 * 4096];       // phi B-frags [b][ch][s 8][nt 8][64]
__device__ uint32_t d_phL[BB * 16 * 4096];
__device__ uint32_t d_gH [BB * 16 * 4096];       // g B-frags [b][ch][kt 4][nt 16][64]
__device__ uint32_t d_gL [BB * 16 * 4096];

#define OW_BASE 49152

// =====================================================================
// Kernel 0: weight prep only (x conversion moved into proj). grid(5).
// =====================================================================
__global__ void __launch_bounds__(256) prep_kernel(
    const float* __restrict__ g_w, const float* __restrict__ th_w,
    const float* __restrict__ ph_w, const float* __restrict__ W_w)
{
    int jt = blockIdx.x, tid = threadIdx.x;
    if (jt < 3) {
        const float* wsel = (jt == 0) ? th_w : (jt == 1) ? ph_w : g_w;
#pragma unroll
        for (int i = 0; i < 64; i++) {
            int e = tid + i * 256;
            int j = e >> 7, kp = e & 127, k0 = 2 * kp;
            float2 v = *(const float2*)&wsel[j * CC + k0];
            uint32_t h, l;
            splitpair(v.x, v.y, h, l);
            int ch = k0 >> 6, kl = k0 & 63;
            int s = kl >> 4, rg = (kl >> 3) & 1, ta = (kl >> 1) & 3;
            int nt = j >> 3, n8 = j & 7;
            int idx = jt * 16384 + ch * 4096 + (s * 16 + nt) * 64 + (n8 * 4 + ta) * 2 + rg;
            d_wpH[idx] = h;
            d_wpL[idx] = l;
        }
    } else {
        int oc0 = (jt - 3) * 128;
#pragma unroll
        for (int i = 0; i < 32; i++) {
            int e = tid + i * 256;
            int oc = e >> 6, kp = e & 63, k0 = 2 * kp;
            float2 v = *(const float2*)&W_w[(oc0 + oc) * ICn + k0];
            uint32_t h, l;
            splitpair(v.x, v.y, h, l);
            int kt = k0 >> 4, rg = (k0 >> 3) & 1, ta = (k0 >> 1) & 3;
            int nt = oc >> 3, n8 = oc & 7;
            int idx = OW_BASE + (jt - 3) * 8192 + (kt * 16 + nt) * 64 + (n8 * 4 + ta) * 2 + rg;
            d_wpH[idx] = h;
            d_wpL[idx] = l;
        }
    }
}

// =====================================================================
// Kernel 1: tri-projection. One CTA per (pt,b) computes theta+phi+g.
// x tile loaded ONCE (cp.async via W staging), converted to resident
// A-frags; 3 jt passes stream only W. grid (32,8), 256 threads.
// smem u32 (50048 = ~195.5KB):
//   XF_H[0,16384) XF_L[16384,32768)
//   WB0[32768,40960) WB1[40960,49152)  (per-buffer: hi 4096 + lo 4096;
//                     also used as fp32 x-chunk staging in prologue)
//   STAGE f32 overlays [32768,49664) pitch 132 x 128
//   BIAS f32 [49664,50048): th[0,128) ph[128,256) g[256,384)
// =====================================================================
#define XF_H 0
#define XF_L 16384
#define WB0  32768
#define WB1  40960
#define P3_STG 32768
#define P3_BIAS 49664
#define P3_U32 50048

__global__ void __launch_bounds__(256) proj3_kernel(
    const float* __restrict__ x,
    const float* __restrict__ g_b, const float* __restrict__ th_b,
    const float* __restrict__ ph_b)
{
    extern __shared__ uint32_t su[];
    float* sf = (float*)su;
    uint32_t sb = smem_u32addr(su);

    int pt = blockIdx.x, b = blockIdx.y;
    int tid = threadIdx.x;
    int w = tid >> 5, lane = tid & 31;
    int gr = lane >> 2, t4 = lane & 3;
    int wM = w >> 1, wN = w & 1;

    if (tid < 128) {
        sf[P3_BIAS + tid]       = th_b[tid];
        sf[P3_BIAS + 128 + tid] = ph_b[tid];
        sf[P3_BIAS + 256 + tid] = g_b[tid];
    }

    // ---- prologue: x tile -> resident A-frags (4 chunks, dbl-buffered) ----
    {
        // issue chunk 0 (fp32) into WB0
#pragma unroll
        for (int i = 0; i < 8; i++) {
            int e = tid + i * 256;
            int kc = e >> 5, p4 = (e & 31) * 4;
            cp_async16(sb + (WB0 + e * 4) * 4,
                       &x[((size_t)b * CC + kc) * NPIX + pt * 128 + p4]);
        }
        CP_COMMIT();

        for (int ch = 0; ch < 4; ch++) {
            if (ch + 1 < 4) {
                int nwb = ((ch + 1) & 1) ? WB1 : WB0;
#pragma unroll
                for (int i = 0; i < 8; i++) {
                    int e = tid + i * 256;
                    int kc = e >> 5, p4 = (e & 31) * 4;
                    cp_async16(sb + (nwb + e * 4) * 4,
                               &x[((size_t)b * CC + (ch + 1) * 64 + kc) * NPIX + pt * 128 + p4]);
                }
                CP_COMMIT();
                CP_WAIT(1);
            } else {
                CP_WAIT(0);
            }
            __syncthreads();

            const float* sx = (const float*)&su[(ch & 1) ? WB1 : WB0];
#pragma unroll
            for (int i = 0; i < 16; i++) {
                int e = tid + i * 256;
                int blk = e >> 7, off = e & 127;
                int ww = blk >> 2, s = blk & 3;
                int gg = off >> 4, ta = (off >> 2) & 3, rg = (off >> 1) & 1, hi8 = off & 1;
                int p = ww * 16 + hi8 * 8 + gg;
                int kl = s * 16 + rg * 8 + ta * 2;
                uint32_t h, l;
                splitpair(sx[kl * 128 + p], sx[(kl + 1) * 128 + p], h, l);
                su[XF_H + ch * 4096 + e] = h;
                su[XF_L + ch * 4096 + e] = l;
            }
            __syncthreads();   // conversion done before buffer reuse
        }
    }

    // ---- 3 jt passes ----
    for (int jt = 0; jt < 3; jt++) {
        int wbase = jt * 16384;

        // issue W chunk 0
        {
#pragma unroll
            for (int i = 0; i < 4; i++) {
                int e4 = (tid + i * 256) * 4;
                cp_async16(sb + (WB0 + e4) * 4,        &d_wpH[wbase + e4]);
                cp_async16(sb + (WB0 + 4096 + e4) * 4, &d_wpL[wbase + e4]);
            }
            CP_COMMIT();
        }

        float acc[2][8][4];
#pragma unroll
        for (int mt = 0; mt < 2; mt++)
#pragma unroll
            for (int nt = 0; nt < 8; nt++)
#pragma unroll
                for (int q = 0; q < 4; q++) acc[mt][nt][q] = 0.f;

        for (int ch = 0; ch < 4; ch++) {
            int wb = (ch & 1) ? WB1 : WB0;
            if (ch + 1 < 4) {
                int nwb = ((ch + 1) & 1) ? WB1 : WB0;
                int wo = wbase + (ch + 1) * 4096;
#pragma unroll
                for (int i = 0; i < 4; i++) {
                    int e4 = (tid + i * 256) * 4;
                    cp_async16(sb + (nwb + e4) * 4,        &d_wpH[wo + e4]);
                    cp_async16(sb + (nwb + 4096 + e4) * 4, &d_wpL[wo + e4]);
                }
                CP_COMMIT();
                CP_WAIT(1);
            } else {
                CP_WAIT(0);
            }
            __syncthreads();

#pragma unroll
            for (int s = 0; s < 4; s++) {
                uint4 ahv[2], alv[2];
#pragma unroll
                for (int mt = 0; mt < 2; mt++) {
                    int ww = wM * 2 + mt;
                    ahv[mt] = *(const uint4*)&su[XF_H + ch * 4096 + (ww * 4 + s) * 128 + lane * 4];
                    alv[mt] = *(const uint4*)&su[XF_L + ch * 4096 + (ww * 4 + s) * 128 + lane * 4];
                }
#pragma unroll
                for (int nt = 0; nt < 8; nt++) {
                    int ntg = wN * 8 + nt;
                    uint2 bhv = *(const uint2*)&su[wb + (s * 16 + ntg) * 64 + lane * 2];
                    uint2 blv = *(const uint2*)&su[wb + 4096 + (s * 16 + ntg) * 64 + lane * 2];
#pragma unroll
                    for (int mt = 0; mt < 2; mt++) {
                        mma16(acc[mt][nt], (const uint32_t*)&ahv[mt], (const uint32_t*)&bhv);
                        mma16(acc[mt][nt], (const uint32_t*)&alv[mt], (const uint32_t*)&bhv);
                        mma16(acc[mt][nt], (const uint32_t*)&ahv[mt], (const uint32_t*)&blv);
                    }
                }
            }
            __syncthreads();
        }

        // ---- epilogue: +bias, stage pitch 132 at P3_STG ----
        float* st = (float*)&su[P3_STG];
#pragma unroll
        for (int mt = 0; mt < 2; mt++)
#pragma unroll
        for (int nt = 0; nt < 8; nt++) {
            int col = wN * 64 + nt * 8 + 2 * t4;
            float b0 = sf[P3_BIAS + jt * 128 + col];
            float b1 = sf[P3_BIAS + jt * 128 + col + 1];
            int ra = (wM * 2 + mt) * 16 + gr, rb = ra + 8;
            st[ra * 132 + col]     = acc[mt][nt][0] + b0;
            st[ra * 132 + col + 1] = acc[mt][nt][1] + b1;
            st[rb * 132 + col]     = acc[mt][nt][2] + b0;
            st[rb * 132 + col + 1] = acc[mt][nt][3] + b1;
        }
        __syncthreads();

        if (jt == 0) {
            size_t base = (size_t)(b * 32 + pt) * 8192;
#pragma unroll
            for (int i = 0; i < 32; i++) {
                int e = tid + i * 256;
                int blk = e >> 7, off = e & 127;
                int ww = blk >> 3, s = blk & 7;
                int gg = off >> 4, ta = (off >> 2) & 3, rg = (off >> 1) & 1, hi8 = off & 1;
                int p = ww * 16 + hi8 * 8 + gg;
                int ic = s * 16 + rg * 8 + ta * 2;
                uint32_t h, l;
                splitpair(st[p * 132 + ic], st[p * 132 + ic + 1], h, l);
                d_thH[base + e] = h;
                d_thL[base + e] = l;
            }
        } else if (jt == 1) {
            int ch = pt >> 1, nthi = (pt & 1) * 4;
            size_t base = (size_t)(b * 16 + ch) * 4096;
#pragma unroll
            for (int i = 0; i < 8; i++) {
                int e = tid + i * 256;
                int s = e >> 8, r = e & 255;
                int ntl = r >> 6, woff = r & 63;
                int n8 = woff >> 3, ta = (woff >> 1) & 3, rg = woff & 1;
                int mc = ntl * 8 + n8;
                int ic = s * 16 + rg * 8 + ta * 2;
                int r0 = 2 * mc, r1 = 2 * mc + 1, r2 = 64 + 2 * mc, r3 = 65 + 2 * mc;
                float v0 = fmaxf(fmaxf(st[r0 * 132 + ic],     st[r1 * 132 + ic]),
                                 fmaxf(st[r2 * 132 + ic],     st[r3 * 132 + ic]));
                float v1 = fmaxf(fmaxf(st[r0 * 132 + ic + 1], st[r1 * 132 + ic + 1]),
                                 fmaxf(st[r2 * 132 + ic + 1], st[r3 * 132 + ic + 1]));
                uint32_t h, l;
                splitpair(v0, v1, h, l);
                size_t idx = base + ((size_t)s * 8 + nthi + ntl) * 64 + woff;
                d_phH[idx] = h;
                d_phL[idx] = l;
            }
        } else {
            int ch = pt >> 1, kthi = (pt & 1) * 2;
            size_t base = (size_t)(b * 16 + ch) * 4096;
#pragma unroll
            for (int i = 0; i < 8; i++) {
                int e = tid + i * 256;
                int ktl = e >> 10, r = e & 1023;
                int nt = r >> 6, woff = r & 63;
                int n8 = woff >> 3, ta = (woff >> 1) & 3, rg = woff & 1;
                int m16 = rg * 8 + ta * 2;
                int mc = ktl * 16 + m16;
                int ic = nt * 8 + n8;
                int ra = 2 * mc, rb = 2 * mc + 1, rc = 64 + 2 * mc, rd = 65 + 2 * mc;
                float v0 = fmaxf(fmaxf(st[ra * 132 + ic], st[rb * 132 + ic]),
                                 fmaxf(st[rc * 132 + ic], st[rd * 132 + ic]));
                ra += 2; rb += 2; rc += 2; rd += 2;
                float v1 = fmaxf(fmaxf(st[ra * 132 + ic], st[rb * 132 + ic]),
                                 fmaxf(st[rc * 132 + ic], st[rd * 132 + ic]));
                uint32_t h, l;
                splitpair(v0, v1, h, l);
                size_t idx = base + ((size_t)(kthi + ktl) * 16 + nt) * 64 + woff;
                d_gH[idx] = h;
                d_gL[idx] = l;
            }
        }
        __syncthreads();   // stage fully read before next jt's W copy
    }
}

// =====================================================================
// Kernel 2: single-wave fused attention + output conv (round-16 passing)
// =====================================================================
#define TH_H 0
#define TH_L 16384
#define PB0  32768
#define PB1  40960
#define GB   49152
#define AT2_U32 57344
#define FB2_INV 33280
#define FB2_ADD 33408
#define WRG  40960

__global__ void __launch_bounds__(256, 1) attn_fused_kernel(
    const float* __restrict__ x,
    const float* __restrict__ Wb,    const float* __restrict__ gamma,
    const float* __restrict__ beta,  const float* __restrict__ bmean,
    const float* __restrict__ bvar,  float* __restrict__ out)
{
    extern __shared__ uint32_t su[];
    float* sf = (float*)su;
    uint32_t sb = smem_u32addr(su);
    int tid = threadIdx.x;
    int w = tid >> 5, lane = tid & 31;
    int gr = lane >> 2, t4 = lane & 3;
    int rt = blockIdx.x, b = blockIdx.y;

    // ---- prologue: theta (2 tiles) + phi0 -> group A; g0 -> group B ----
    {
        size_t tb = (size_t)(b * 32 + rt * 2) * 8192;
#pragma unroll
        for (int i = 0; i < 16; i++) {
            int e4 = (tid + i * 256) * 4;
            cp_async16(sb + (TH_H + e4) * 4, &d_thH[tb + e4]);
            cp_async16(sb + (TH_L + e4) * 4, &d_thL[tb + e4]);
        }
        size_t base = (size_t)(b * 16) * 4096;
#pragma unroll
        for (int i = 0; i < 4; i++) {
            int e4 = (tid + i * 256) * 4;
            cp_async16(sb + (PB0 + e4) * 4,        &d_phH[base + e4]);
            cp_async16(sb + (PB0 + 4096 + e4) * 4, &d_phL[base + e4]);
        }
        CP_COMMIT();
#pragma unroll
        for (int i = 0; i < 4; i++) {
            int e4 = (tid + i * 256) * 4;
            cp_async16(sb + (GB + e4) * 4,        &d_gH[base + e4]);
            cp_async16(sb + (GB + 4096 + e4) * 4, &d_gL[base + e4]);
        }
        CP_COMMIT();
    }

    float yacc[2][16][4];
#pragma unroll
    for (int mt = 0; mt < 2; mt++)
#pragma unroll
        for (int nt = 0; nt < 16; nt++)
#pragma unroll
            for (int q = 0; q < 4; q++) yacc[mt][nt][q] = 0.f;
    float ls00 = 0.f, ls01 = 0.f, ls10 = 0.f, ls11 = 0.f;

    for (int ch = 0; ch < 16; ch++) {
        int pb = (ch & 1) ? PB1 : PB0;
        CP_WAIT(1);
        __syncthreads();

        float sacc[2][8][4];
#pragma unroll
        for (int mt = 0; mt < 2; mt++)
#pragma unroll
            for (int nt = 0; nt < 8; nt++)
#pragma unroll
                for (int q = 0; q < 4; q++) sacc[mt][nt][q] = 0.f;

#pragma unroll
        for (int s = 0; s < 8; s++) {
            uint4 ah0 = *(const uint4*)&su[TH_H + ((w * 2 + 0) * 8 + s) * 128 + lane * 4];
            uint4 al0 = *(const uint4*)&su[TH_L + ((w * 2 + 0) * 8 + s) * 128 + lane * 4];
            uint4 ah1 = *(const uint4*)&su[TH_H + ((w * 2 + 1) * 8 + s) * 128 + lane * 4];
            uint4 al1 = *(const uint4*)&su[TH_L + ((w * 2 + 1) * 8 + s) * 128 + lane * 4];
#pragma unroll
            for (int nt = 0; nt < 8; nt++) {
                uint2 bhv = *(const uint2*)&su[pb + (s * 8 + nt) * 64 + lane * 2];
                uint2 blv = *(const uint2*)&su[pb + 4096 + (s * 8 + nt) * 64 + lane * 2];
                mma16(sacc[0][nt], (const uint32_t*)&ah0, (const uint32_t*)&bhv);
                mma16(sacc[0][nt], (const uint32_t*)&al0, (const uint32_t*)&bhv);
                mma16(sacc[0][nt], (const uint32_t*)&ah0, (const uint32_t*)&blv);
                mma16(sacc[1][nt], (const uint32_t*)&ah1, (const uint32_t*)&bhv);
                mma16(sacc[1][nt], (const uint32_t*)&al1, (const uint32_t*)&bhv);
                mma16(sacc[1][nt], (const uint32_t*)&ah1, (const uint32_t*)&blv);
            }
        }

        CP_WAIT(0);
        __syncthreads();

        if (ch + 1 < 16) {
            int npb = ((ch + 1) & 1) ? PB1 : PB0;
            size_t base = (size_t)(b * 16 + ch + 1) * 4096;
#pragma unroll
            for (int i = 0; i < 4; i++) {
                int e4 = (tid + i * 256) * 4;
                cp_async16(sb + (npb + e4) * 4,        &d_phH[base + e4]);
                cp_async16(sb + (npb + 4096 + e4) * 4, &d_phL[base + e4]);
            }
            CP_COMMIT();
        } else {
#pragma unroll
            for (int i = 0; i < 8; i++) {
                int e4 = (tid + i * 256) * 4;
                cp_async16(sb + (WRG + e4) * 4, &d_wpH[OW_BASE + e4]);
            }
            CP_COMMIT();
        }

#pragma unroll
        for (int kt = 0; kt < 4; kt++) {
            uint32_t ah[2][4], al[2][4];
#pragma unroll
            for (int mt = 0; mt < 2; mt++) {
#pragma unroll
                for (int j = 0; j < 2; j++) {
                    int nt = 2 * kt + j;
                    float p0 = __expf(sacc[mt][nt][0] - 40.f);
                    float p1 = __expf(sacc[mt][nt][1] - 40.f);
                    float p2 = __expf(sacc[mt][nt][2] - 40.f);
                    float p3 = __expf(sacc[mt][nt][3] - 40.f);
                    if (mt == 0) { ls00 += p0 + p1; ls01 += p2 + p3; }
                    else         { ls10 += p0 + p1; ls11 += p2 + p3; }
                    splitpair(p0, p1, ah[mt][2 * j],     al[mt][2 * j]);
                    splitpair(p2, p3, ah[mt][2 * j + 1], al[mt][2 * j + 1]);
                }
            }
#pragma unroll
            for (int nt = 0; nt < 16; nt++) {
                uint2 ghv = *(const uint2*)&su[GB + (kt * 16 + nt) * 64 + lane * 2];
                uint2 glv = *(const uint2*)&su[GB + 4096 + (kt * 16 + nt) * 64 + lane * 2];
                mma16(yacc[0][nt], ah[0], (const uint32_t*)&ghv);
                mma16(yacc[0][nt], al[0], (const uint32_t*)&ghv);
                mma16(yacc[0][nt], ah[0], (const uint32_t*)&glv);
                mma16(yacc[1][nt], ah[1], (const uint32_t*)&ghv);
                mma16(yacc[1][nt], al[1], (const uint32_t*)&ghv);
                mma16(yacc[1][nt], ah[1], (const uint32_t*)&glv);
            }
        }
        __syncthreads();

        if (ch + 1 < 16) {
            size_t base = (size_t)(b * 16 + ch + 1) * 4096;
#pragma unroll
            for (int i = 0; i < 4; i++) {
                int e4 = (tid + i * 256) * 4;
                cp_async16(sb + (GB + e4) * 4,        &d_gH[base + e4]);
                cp_async16(sb + (GB + 4096 + e4) * 4, &d_gL[base + e4]);
            }
            CP_COMMIT();
        } else {
#pragma unroll
            for (int i = 0; i < 8; i++) {
                int e4 = (tid + i * 256) * 4;
                cp_async16(sb + (GB + e4) * 4, &d_wpL[OW_BASE + e4]);
            }
            CP_COMMIT();
        }
    }

    // ---- normalize; convert yacc -> y A-frags ----
    ls00 += __shfl_xor_sync(0xffffffffu, ls00, 1);
    ls00 += __shfl_xor_sync(0xffffffffu, ls00, 2);
    ls01 += __shfl_xor_sync(0xffffffffu, ls01, 1);
    ls01 += __shfl_xor_sync(0xffffffffu, ls01, 2);
    ls10 += __shfl_xor_sync(0xffffffffu, ls10, 1);
    ls10 += __shfl_xor_sync(0xffffffffu, ls10, 2);
    ls11 += __shfl_xor_sync(0xffffffffu, ls11, 1);
    ls11 += __shfl_xor_sync(0xffffffffu, ls11, 2);
    float inv00 = 1.f / ls00, inv01 = 1.f / ls01;
    float inv10 = 1.f / ls10, inv11 = 1.f / ls11;

    uint32_t yh[2][8][4], yl[2][8][4];
#pragma unroll
    for (int mt = 0; mt < 2; mt++) {
        float i0 = (mt == 0) ? inv00 : inv10;
        float i1 = (mt == 0) ? inv01 : inv11;
#pragma unroll
        for (int kt = 0; kt < 8; kt++) {
            splitpair(yacc[mt][2 * kt][0] * i0, yacc[mt][2 * kt][1] * i0, yh[mt][kt][0], yl[mt][kt][0]);
            splitpair(yacc[mt][2 * kt][2] * i1, yacc[mt][2 * kt][3] * i1, yh[mt][kt][1], yl[mt][kt][1]);
            splitpair(yacc[mt][2 * kt + 1][0] * i0, yacc[mt][2 * kt + 1][1] * i0, yh[mt][kt][2], yl[mt][kt][2]);
            splitpair(yacc[mt][2 * kt + 1][2] * i1, yacc[mt][2 * kt + 1][3] * i1, yh[mt][kt][3], yl[mt][kt][3]);
        }
    }

    CP_WAIT(0);
    __syncthreads();
    if (tid < 128) {
        float bninv = gamma[tid] * rsqrtf(bvar[tid] + 1e-5f);
        sf[FB2_INV + tid] = bninv;
        sf[FB2_ADD + tid] = (Wb[tid] - bmean[tid]) * bninv + beta[tid];
    }
    __syncthreads();

    for (int jt = 0; jt < 2; jt++) {
        int oc0 = jt * 128;

#pragma unroll
        for (int mt = 0; mt < 2; mt++) {
            float oacc[16][4];
#pragma unroll
            for (int nt = 0; nt < 16; nt++)
#pragma unroll
                for (int q = 0; q < 4; q++) oacc[nt][q] = 0.f;

#pragma unroll
            for (int kt = 0; kt < 8; kt++) {
#pragma unroll
                for (int nt = 0; nt < 16; nt++) {
                    uint2 bhv = *(const uint2*)&su[WRG + (kt * 16 + nt) * 64 + lane * 2];
                    uint2 blv = *(const uint2*)&su[GB + (kt * 16 + nt) * 64 + lane * 2];
                    mma16(oacc[nt], yh[mt][kt], (const uint32_t*)&bhv);
                    mma16(oacc[nt], yl[mt][kt], (const uint32_t*)&bhv);
                    mma16(oacc[nt], yh[mt][kt], (const uint32_t*)&blv);
                }
            }

#pragma unroll
            for (int nt = 0; nt < 16; nt++) {
                int col = nt * 8 + 2 * t4;
                float i0 = sf[FB2_INV + col], i1 = sf[FB2_INV + col + 1];
                float a0 = sf[FB2_ADD + col], a1 = sf[FB2_ADD + col + 1];
                int ra = w * 32 + mt * 16 + gr, rb = ra + 8;
                sf[ra * 130 + col]     = oacc[nt][0] * i0 + a0;
                sf[ra * 130 + col + 1] = oacc[nt][1] * i1 + a1;
                sf[rb * 130 + col]     = oacc[nt][2] * i0 + a0;
                sf[rb * 130 + col + 1] = oacc[nt][3] * i1 + a1;
            }
        }
        __syncthreads();

        if (jt == 0) {
#pragma unroll
            for (int i = 0; i < 8; i++) {
                int e4 = (tid + i * 256) * 4;
                cp_async16(sb + (WRG + e4) * 4, &d_wpH[OW_BASE + 8192 + e4]);
                cp_async16(sb + (GB + e4) * 4,  &d_wpL[OW_BASE + 8192 + e4]);
            }
            CP_COMMIT();
        }

        const float* xr = x + ((size_t)b * CC + oc0) * NPIX + rt * 256;
        float* outp = out + ((size_t)b * CC + oc0) * NPIX + rt * 256;
#pragma unroll
        for (int i = 0; i < 32; i++) {
            int e = tid + i * 256;
            int oc = e >> 6, pq = (e & 63) * 4;
            float4 xv = *(const float4*)&xr[(size_t)oc * NPIX + pq];
            float4 v = make_float4(sf[(pq + 0) * 130 + oc] + xv.x,
                                   sf[(pq + 1) * 130 + oc] + xv.y,
                                   sf[(pq + 2) * 130 + oc] + xv.z,
                                   sf[(pq + 3) * 130 + oc] + xv.w);
            *(float4*)&outp[(size_t)oc * NPIX + pq] = v;
        }

        if (jt == 0) {
            CP_WAIT(0);
            __syncthreads();
            if (tid < 128) {
                int oc = 128 + tid;
                float bninv = gamma[oc] * rsqrtf(bvar[oc] + 1e-5f);
                sf[FB2_INV + tid] = bninv;
                sf[FB2_ADD + tid] = (Wb[oc] - bmean[oc]) * bninv + beta[oc];
            }
            __syncthreads();
        }
    }
}

// =====================================================================
extern "C" void kernel_launch(void* const* d_in, const int* in_sizes, int n_in,
                              void* d_out, int out_size)
{
    (void)in_sizes; (void)n_in; (void)out_size;
    const float* x    = (const float*)d_in[0];
    const float* g_w  = (const float*)d_in[1];
    const float* g_b  = (const float*)d_in[2];
    const float* th_w = (const float*)d_in[3];
    const float* th_b = (const float*)d_in[4];
    const float* ph_w = (const float*)d_in[5];
    const float* ph_b = (const float*)d_in[6];
    const float* W_w  = (const float*)d_in[7];
    const float* W_b  = (const float*)d_in[8];
    const float* bg   = (const float*)d_in[9];
    const float* bbta = (const float*)d_in[10];
    const float* bm   = (const float*)d_in[11];
    const float* bv   = (const float*)d_in[12];
    float* out = (float*)d_out;

    static int configured = 0;
    if (!configured) {
        cudaFuncSetAttribute(proj3_kernel,
            cudaFuncAttributeMaxDynamicSharedMemorySize, P3_U32 * 4);
        cudaFuncSetAttribute(attn_fused_kernel,
            cudaFuncAttributeMaxDynamicSharedMemorySize, AT2_U32 * 4);
        configured = 1;
    }

    prep_kernel<<<5, 256>>>(g_w, th_w, ph_w, W_w);

    proj3_kernel<<<dim3(32, 8), 256, P3_U32 * 4>>>(x, g_b, th_b, ph_b);

    attn_fused_kernel<<<dim3(16, 8), 256, AT2_U32 * 4>>>(
        x, W_b, bg, bbta, bm, bv, out);
}